// round 1
// baseline (speedup 1.0000x reference)
#include <cuda_runtime.h>

#define CIN   64
#define CO    64
#define HH    32
#define WW    32
#define KK    7
#define GG    8
#define PW    38            // padded width (32 + 2*3)
#define NPIX  1024          // 32*32
#define NPAD  (PW*PW)       // 1444

typedef unsigned long long ull;

__device__ __forceinline__ ull ffma2(ull a, ull b, ull c) {
    ull d;
    asm("fma.rn.f32x2 %0, %1, %2, %3;" : "=l"(d) : "l"(a), "l"(b), "l"(c));
    return d;
}
__device__ __forceinline__ ull pk2(float a, float b) {
    ull r;
    asm("mov.b64 %0, {%1, %2};" : "=l"(r) : "f"(a), "f"(b));
    return r;
}
__device__ __forceinline__ float2 upk2(ull v) {
    float2 t;
    asm("mov.b64 {%0, %1}, %2;" : "=f"(t.x), "=f"(t.y) : "l"(v));
    return t;
}

// One CTA per (batch b, group g). 512 threads.
// Phase 1: project q/k/v for this group's 8 channels (fp32, f32x2-packed FMA).
// Phase 2: 7x7 local attention with single-pass (max-free) softmax + ring mask.
__global__ __launch_bounds__(512, 1)
void attn_conv_fused(const float* __restrict__ x,
                     const float* __restrict__ wq,
                     const float* __restrict__ wk,
                     const float* __restrict__ wv,
                     const float* __restrict__ relh,
                     const float* __restrict__ relw,
                     const float* __restrict__ cval,
                     float* __restrict__ out)
{
    extern __shared__ float smem[];
    // two float4 planes per tensor (ch0-3, ch4-7) -> conflict-free LDS.128
    ulonglong2* ktA = (ulonglong2*)smem;       // [NPAD]
    ulonglong2* ktB = ktA + NPAD;
    ulonglong2* vtA = ktB + NPAD;
    ulonglong2* vtB = vtA + NPAD;
    ulonglong2* qsA = vtB + NPAD;              // [NPIX]
    ulonglong2* qsB = qsA + NPIX;
    float* wt   = (float*)(qsB + NPIX);        // [64 ci][24] : q0-7,k0-7,v0-7
    float* rels = wt + 64*24;                  // [7][8]

    const int g   = blockIdx.x;
    const int b   = blockIdx.y;
    const int tid = threadIdx.x;

    // ---- stage weights (transposed: ci-major) ----
    for (int idx = tid; idx < 64*24; idx += 512) {
        int ci = idx / 24, c = idx % 24;
        float v;
        if (c < 8)       v = wq[(g*8 + c)        * 64 + ci];
        else if (c < 16) v = wk[(g*8 + (c - 8))  * 64 + ci];
        else             v = wv[(g*8 + (c - 16)) * 64 + ci];
        wt[idx] = v;
    }
    // rel-pos slice for this group: groups 0-3 use rel_h (row-indexed),
    // groups 4-7 use rel_w (col-indexed). Layout rels[i][c].
    if (tid < 56) {
        int i = tid >> 3, c = tid & 7;
        rels[tid] = (g < 4) ? relh[(g*8 + c)*7 + i]
                            : relw[((g - 4)*8 + c)*7 + i];
    }
    // zero padded k/v tiles (borders stay zero = zero-padded conv)
    {
        ulonglong2 z; z.x = 0ULL; z.y = 0ULL;
        for (int idx = tid; idx < NPAD; idx += 512) {
            ktA[idx] = z; ktB[idx] = z; vtA[idx] = z; vtB[idx] = z;
        }
    }
    __syncthreads();

    // ---- Phase 1: projection, 2 pixels per thread ----
    {
        ull acc0[12], acc1[12];
        #pragma unroll
        for (int i2 = 0; i2 < 12; i2++) { acc0[i2] = 0ULL; acc1[i2] = 0ULL; }

        const float* xb = x + (size_t)b * CIN * NPIX;
        #pragma unroll 8
        for (int ci = 0; ci < 64; ci++) {
            float x0 = xb[ci*NPIX + tid];
            float x1 = xb[ci*NPIX + 512 + tid];
            ull x0p = pk2(x0, x0);
            ull x1p = pk2(x1, x1);
            const ulonglong2* wrow = (const ulonglong2*)(wt + ci*24);
            #pragma unroll
            for (int p = 0; p < 6; p++) {
                ulonglong2 wv2 = wrow[p];
                acc0[2*p]   = ffma2(x0p, wv2.x, acc0[2*p]);
                acc0[2*p+1] = ffma2(x0p, wv2.y, acc0[2*p+1]);
                acc1[2*p]   = ffma2(x1p, wv2.x, acc1[2*p]);
                acc1[2*p+1] = ffma2(x1p, wv2.y, acc1[2*p+1]);
            }
        }
        #pragma unroll
        for (int pp = 0; pp < 2; pp++) {
            ull* acc = pp ? acc1 : acc0;
            int p  = tid + pp*512;
            int h  = p >> 5, w = p & 31;
            int pi = (h + 3)*PW + (w + 3);
            ulonglong2 t;
            t.x = acc[0];  t.y = acc[1];  qsA[p]  = t;   // q ch0-3
            t.x = acc[2];  t.y = acc[3];  qsB[p]  = t;   // q ch4-7
            t.x = acc[4];  t.y = acc[5];  ktA[pi] = t;   // k ch0-3
            t.x = acc[6];  t.y = acc[7];  ktB[pi] = t;   // k ch4-7
            t.x = acc[8];  t.y = acc[9];  vtA[pi] = t;   // v ch0-3
            t.x = acc[10]; t.y = acc[11]; vtB[pi] = t;   // v ch4-7
        }
    }
    __syncthreads();

    // ---- Phase 2: attention ----
    const bool  isH  = (g < 4);
    const float cvg  = cval[g];
    const int   warp = tid >> 5, lane = tid & 31;
    float* outbase = out + ((size_t)b * CO + g * 8) * NPIX;

    for (int rep = 0; rep < 2; rep++) {
        const int h   = warp + rep*16;
        const int w   = lane;
        const int pos = h*32 + w;

        ulonglong2 Q0 = qsA[pos];
        ulonglong2 Q1 = qsB[pos];
        float2 q01 = upk2(Q0.x), q23 = upk2(Q0.y);
        float2 q45 = upk2(Q1.x), q67 = upk2(Q1.y);
        float qv[8] = {q01.x, q01.y, q23.x, q23.y, q45.x, q45.y, q67.x, q67.y};

        float bias[7];
        #pragma unroll
        for (int i = 0; i < 7; i++) {
            float s = 0.f;
            #pragma unroll
            for (int c = 0; c < 8; c++) s = fmaf(qv[c], rels[i*8 + c], s);
            bias[i] = s;
        }

        float Z = 0.f;
        ull a01 = 0ULL, a23 = 0ULL, a45 = 0ULL, a67 = 0ULL;
        const int base = h*PW + w;
        #pragma unroll
        for (int i = 0; i < 7; i++) {
            #pragma unroll
            for (int j = 0; j < 7; j++) {
                const int o = base + i*PW + j;
                ulonglong2 ka = ktA[o], kb = ktB[o];
                ull s2 = ffma2(Q0.x, ka.x,
                         ffma2(Q0.y, ka.y,
                         ffma2(Q1.x, kb.x,
                         ffma2(Q1.y, kb.y, 0ULL))));
                float2 sf = upk2(s2);
                float s = sf.x + sf.y + (isH ? bias[i] : bias[j]);
                float e = __expf(s);   // max-free: |s| < ~40 << fp32 exp range
                Z += e;
                ull e2 = pk2(e, e);
                ulonglong2 va = vtA[o], vb = vtB[o];
                a01 = ffma2(e2, va.x, a01);
                a23 = ffma2(e2, va.y, a23);
                a45 = ffma2(e2, vb.x, a45);
                a67 = ffma2(e2, vb.y, a67);
            }
        }

        // adaptive ring mask
        int r  = min(h, 31 - h);
        int lo = (h <= 31 - h) ? r : r + 1;
        int hi = 31 - r;
        float omv  = fminf(fmaxf(((float)(r - 15) + cvg*16.0f) * (1.0f/3.0f) + 1.0f,
                                 0.0f), 1.0f);
        float mval = (w >= lo && w <= hi) ? omv : 1.0f;
        float sc   = __fdividef(mval, Z);

        float2 o01 = upk2(a01), o23 = upk2(a23), o45 = upk2(a45), o67 = upk2(a67);
        outbase[0*NPIX + pos] = o01.x * sc;
        outbase[1*NPIX + pos] = o01.y * sc;
        outbase[2*NPIX + pos] = o23.x * sc;
        outbase[3*NPIX + pos] = o23.y * sc;
        outbase[4*NPIX + pos] = o45.x * sc;
        outbase[5*NPIX + pos] = o45.y * sc;
        outbase[6*NPIX + pos] = o67.x * sc;
        outbase[7*NPIX + pos] = o67.y * sc;
    }
}

#define SMEM_BYTES ((4*NPAD + 2*NPIX)*16 + 64*24*4 + 56*4)

extern "C" void kernel_launch(void* const* d_in, const int* in_sizes, int n_in,
                              void* d_out, int out_size)
{
    const float* x    = (const float*)d_in[0];
    const float* wq   = (const float*)d_in[1];
    const float* wk   = (const float*)d_in[2];
    const float* wv   = (const float*)d_in[3];
    const float* relh = (const float*)d_in[4];
    const float* relw = (const float*)d_in[5];
    const float* cv   = (const float*)d_in[6];
    float* out = (float*)d_out;

    cudaFuncSetAttribute(attn_conv_fused,
                         cudaFuncAttributeMaxDynamicSharedMemorySize, SMEM_BYTES);
    attn_conv_fused<<<dim3(GG, 32), 512, SMEM_BYTES>>>(x, wq, wk, wv, relh, relw, cv, out);
}

// round 2
// speedup vs baseline: 1.3592x; 1.3592x over previous
#include <cuda_runtime.h>

#define CIN   64
#define PW    38            // padded width (32 + 2*3)
#define NPIX  1024          // 32*32
#define NPAD  (PW*PW)       // 1444

#define PLANES_BYTES (4*NPAD*16)              // ktA,ktB,vtA,vtB
#define COPY_BYTES   (PLANES_BYTES + 1536*4 + 224)  // + wt + rels = 98784

typedef unsigned long long ull;

__device__ __forceinline__ ull ffma2(ull a, ull b, ull c) {
    ull d;
    asm("fma.rn.f32x2 %0, %1, %2, %3;" : "=l"(d) : "l"(a), "l"(b), "l"(c));
    return d;
}
__device__ __forceinline__ ull pk2(float a, float b) {
    ull r;
    asm("mov.b64 %0, {%1, %2};" : "=l"(r) : "f"(a), "f"(b));
    return r;
}
__device__ __forceinline__ float2 upk2(ull v) {
    float2 t;
    asm("mov.b64 {%0, %1}, %2;" : "=f"(t.x), "=f"(t.y) : "l"(v));
    return t;
}

// One CTA per (batch b, group-pair gp). 512 threads = 2 halves x 8 warps.
// Each half handles one group; each thread owns a column of 4 output rows.
// Phase 1: project q/k/v (f32x2 FMA), q -> registers, k/v -> smem.
// Phase 2: R=4 row-blocked 7x7 local attention (2.8x LDS reuse) + ring mask.
__global__ __launch_bounds__(512, 1)
void attn_conv_fused(const float* __restrict__ x,
                     const float* __restrict__ wq,
                     const float* __restrict__ wk,
                     const float* __restrict__ wv,
                     const float* __restrict__ relh,
                     const float* __restrict__ relw,
                     const float* __restrict__ cval,
                     float* __restrict__ out)
{
    extern __shared__ char smem[];

    const int gp  = blockIdx.x;        // group pair 0..3
    const int b   = blockIdx.y;
    const int tid = threadIdx.x;
    const int half = tid >> 8;         // which group of the pair
    const int t    = tid & 255;
    const int wr2  = t >> 5;           // warp within half: 0..7
    const int w    = t & 31;           // column
    const int h0   = wr2 * 4;          // first of 4 owned rows
    const int g    = gp * 2 + half;    // global group

    // ---- stage weights (transposed ci-major) for both groups ----
    for (int idx = tid; idx < 2 * 1536; idx += 512) {
        int copy = idx / 1536;
        int k2   = idx - copy * 1536;
        int ci = k2 / 24, c = k2 % 24;
        int gg = gp * 2 + copy;
        float v;
        if (c < 8)       v = wq[(gg*8 + c)        * 64 + ci];
        else if (c < 16) v = wk[(gg*8 + (c - 8))  * 64 + ci];
        else             v = wv[(gg*8 + (c - 16)) * 64 + ci];
        ((float*)(smem + copy*COPY_BYTES + PLANES_BYTES))[k2] = v;
    }
    if (tid < 112) {
        int copy = tid / 56, r = tid % 56;
        int i = r >> 3, c = r & 7;
        int gg = gp * 2 + copy;
        float v = (gg < 4) ? relh[(gg*8 + c)*7 + i]
                           : relw[((gg - 4)*8 + c)*7 + i];
        ((float*)(smem + copy*COPY_BYTES + PLANES_BYTES + 1536*4))[r] = v;
    }
    // zero padded k/v planes (borders act as zero padding)
    {
        ulonglong2 z; z.x = 0ULL; z.y = 0ULL;
        #pragma unroll
        for (int copy = 0; copy < 2; copy++) {
            ulonglong2* pl = (ulonglong2*)(smem + copy*COPY_BYTES);
            for (int idx = tid; idx < 4*NPAD; idx += 512) pl[idx] = z;
        }
    }
    __syncthreads();

    // pointers into this half's copy
    ulonglong2* ktA = (ulonglong2*)(smem + half*COPY_BYTES);
    ulonglong2* ktB = ktA + NPAD;
    ulonglong2* vtA = ktB + NPAD;
    ulonglong2* vtB = vtA + NPAD;
    const float* wt   = (const float*)(smem + half*COPY_BYTES + PLANES_BYTES);
    const ulonglong2* relp = (const ulonglong2*)(wt + 1536);  // [7][2]

    // ---- Phase 1: projection for the 4 owned pixels (2 passes of 2 rows) ----
    ull   Q[4][4];       // q, 8 ch packed, per owned output
    float bias[4][7];    // q . rel  per tap index
    const float* xb = x + (size_t)b * CIN * NPIX;

    #pragma unroll
    for (int pass = 0; pass < 2; pass++) {
        const int r0 = h0 + 2*pass;
        ull acc[2][12];
        #pragma unroll
        for (int e = 0; e < 2; e++)
            #pragma unroll
            for (int p = 0; p < 12; p++) acc[e][p] = 0ULL;

        #pragma unroll 4
        for (int ci = 0; ci < 64; ci++) {
            float x0 = xb[ci*NPIX + r0*32 + w];
            float x1 = xb[ci*NPIX + (r0+1)*32 + w];
            ull xp0 = pk2(x0, x0);
            ull xp1 = pk2(x1, x1);
            const ulonglong2* wrow = (const ulonglong2*)(wt + ci*24);
            #pragma unroll
            for (int p = 0; p < 6; p++) {
                ulonglong2 wv2 = wrow[p];
                acc[0][2*p]   = ffma2(xp0, wv2.x, acc[0][2*p]);
                acc[0][2*p+1] = ffma2(xp0, wv2.y, acc[0][2*p+1]);
                acc[1][2*p]   = ffma2(xp1, wv2.x, acc[1][2*p]);
                acc[1][2*p+1] = ffma2(xp1, wv2.y, acc[1][2*p+1]);
            }
        }
        #pragma unroll
        for (int e = 0; e < 2; e++) {
            const int o = 2*pass + e;
            Q[o][0] = acc[e][0]; Q[o][1] = acc[e][1];
            Q[o][2] = acc[e][2]; Q[o][3] = acc[e][3];
            #pragma unroll
            for (int i = 0; i < 7; i++) {
                ulonglong2 r01 = relp[i*2], r23 = relp[i*2 + 1];
                ull d = ffma2(Q[o][0], r01.x,
                        ffma2(Q[o][1], r01.y,
                        ffma2(Q[o][2], r23.x,
                        ffma2(Q[o][3], r23.y, 0ULL))));
                float2 df = upk2(d);
                bias[o][i] = df.x + df.y;
            }
            const int pi = (h0 + o + 3)*PW + (w + 3);
            ulonglong2 tkv;
            tkv.x = acc[e][4];  tkv.y = acc[e][5];  ktA[pi] = tkv;
            tkv.x = acc[e][6];  tkv.y = acc[e][7];  ktB[pi] = tkv;
            tkv.x = acc[e][8];  tkv.y = acc[e][9];  vtA[pi] = tkv;
            tkv.x = acc[e][10]; tkv.y = acc[e][11]; vtB[pi] = tkv;
        }
    }
    __syncthreads();

    // ---- Phase 2: row-blocked attention (4 outputs share window rows) ----
    const bool isH = (gp < 2);
    float Z[4] = {0.f, 0.f, 0.f, 0.f};
    ull aa[4][4];
    #pragma unroll
    for (int o = 0; o < 4; o++)
        #pragma unroll
        for (int p = 0; p < 4; p++) aa[o][p] = 0ULL;

    #pragma unroll
    for (int pr = 0; pr < 10; pr++) {         // padded window rows h0..h0+9
        const int rowoff = (h0 + pr)*PW + w;
        #pragma unroll
        for (int j = 0; j < 7; j++) {
            const int off = rowoff + j;
            ulonglong2 ka = ktA[off], kb = ktB[off];
            ulonglong2 va = vtA[off], vb = vtB[off];
            #pragma unroll
            for (int o = 0; o < 4; o++) {
                const int i = pr - o;          // tap row for output o
                if (i >= 0 && i < 7) {
                    ull s2 = ffma2(Q[o][0], ka.x,
                             ffma2(Q[o][1], ka.y,
                             ffma2(Q[o][2], kb.x,
                             ffma2(Q[o][3], kb.y, 0ULL))));
                    float2 sf = upk2(s2);
                    float s = sf.x + sf.y + (isH ? bias[o][i] : bias[o][j]);
                    float e = __expf(s);       // max-free: |s| << fp32 exp range
                    Z[o] += e;
                    ull e2 = pk2(e, e);
                    aa[o][0] = ffma2(e2, va.x, aa[o][0]);
                    aa[o][1] = ffma2(e2, va.y, aa[o][1]);
                    aa[o][2] = ffma2(e2, vb.x, aa[o][2]);
                    aa[o][3] = ffma2(e2, vb.y, aa[o][3]);
                }
            }
        }
    }

    // ---- epilogue: adaptive ring mask + normalize + store ----
    const float cvg = cval[g];
    float* outbase = out + ((size_t)b * 64 + g * 8) * NPIX;
    #pragma unroll
    for (int o = 0; o < 4; o++) {
        const int h   = h0 + o;
        const int pos = h*32 + w;
        int r  = min(h, 31 - h);
        int lo = (h <= 31 - h) ? r : r + 1;
        int hi = 31 - r;
        float omv  = fminf(fmaxf(((float)(r - 15) + cvg*16.0f)*(1.0f/3.0f) + 1.0f,
                                 0.0f), 1.0f);
        float mval = (w >= lo && w <= hi) ? omv : 1.0f;
        float sc   = __fdividef(mval, Z[o]);

        float2 o01 = upk2(aa[o][0]), o23 = upk2(aa[o][1]);
        float2 o45 = upk2(aa[o][2]), o67 = upk2(aa[o][3]);
        outbase[0*NPIX + pos] = o01.x * sc;
        outbase[1*NPIX + pos] = o01.y * sc;
        outbase[2*NPIX + pos] = o23.x * sc;
        outbase[3*NPIX + pos] = o23.y * sc;
        outbase[4*NPIX + pos] = o45.x * sc;
        outbase[5*NPIX + pos] = o45.y * sc;
        outbase[6*NPIX + pos] = o67.x * sc;
        outbase[7*NPIX + pos] = o67.y * sc;
    }
}

#define SMEM_BYTES (2*COPY_BYTES)

extern "C" void kernel_launch(void* const* d_in, const int* in_sizes, int n_in,
                              void* d_out, int out_size)
{
    const float* x    = (const float*)d_in[0];
    const float* wq   = (const float*)d_in[1];
    const float* wk   = (const float*)d_in[2];
    const float* wv   = (const float*)d_in[3];
    const float* relh = (const float*)d_in[4];
    const float* relw = (const float*)d_in[5];
    const float* cv   = (const float*)d_in[6];
    float* out = (float*)d_out;

    cudaFuncSetAttribute(attn_conv_fused,
                         cudaFuncAttributeMaxDynamicSharedMemorySize, SMEM_BYTES);
    attn_conv_fused<<<dim3(4, 32), 512, SMEM_BYTES>>>(x, wq, wk, wv, relh, relw, cv, out);
}